// round 11
// baseline (speedup 1.0000x reference)
#include <cuda_runtime.h>
#include <math.h>

#define HIDDEN   2048
#define NQ       8
#define HD       256
#define QKV_ROWS 2560   // (8 + 2) * 256
#define SEQ      8192
#define LAYER    5
#define CHUNK    32
#define NCHUNK   256    // SEQ / CHUNK
#define OW32     (HIDDEN * HIDDEN * 4 / 32)  // o_w in 32B units = 524288
#define PREF_BLK 320
#define QKV_BLK  (QKV_ROWS / 2)          // 1280
#define PHASEA_GRID (QKV_BLK + PREF_BLK) // 1600

// ---------------- scratch (device globals; no allocation) ----------------
__device__ __align__(16) float g_qkv[QKV_ROWS];
__device__ __align__(16) float g_part[NCHUNK * NQ * HD];
__device__ __align__(16) float g_l[NCHUNK * NQ];
__device__ __align__(16) float g_attn[NQ * HD];
__device__ float g_dummy;

__device__ __forceinline__ float warp_sum(float v) {
#pragma unroll
    for (int o = 16; o; o >>= 1) v += __shfl_xor_sync(0xffffffffu, v, o);
    return v;
}
__device__ __forceinline__ float warp_max(float v) {
#pragma unroll
    for (int o = 16; o; o >>= 1) v = fmaxf(v, __shfl_xor_sync(0xffffffffu, v, o));
    return v;
}
__device__ __forceinline__ float dot4(float4 a, float4 b) {
    return a.x * b.x + a.y * b.y + a.z * b.z + a.w * b.w;
}

// ---------------- phase A: qkv GEMV + interleaved o_w L2 prefetch ----------
// Every 5th block streams a slice of o_w into L2 with evict_last (32B loads);
// the other 1280 blocks do the qkv GEMV (R4 config: 2 rows/block,
// 128 thr/row, evict-first W loads so they don't displace o_w).
__global__ void qkv_pref_kernel(const float* __restrict__ W,
                                const float* __restrict__ x,
                                float* __restrict__ y,
                                const float* __restrict__ ow) {
    int tid = threadIdx.x;
    int bid = blockIdx.x;

    if ((bid % 5) == 4) {
        // ---- o_w prefetch block (32B evict_last loads) ----
        int pb = bid / 5;                        // 0..319
        const char* obase = reinterpret_cast<const char*>(ow);
        unsigned long long s = 0;
        for (long long i = pb * 256 + tid; i < OW32; i += (long long)PREF_BLK * 256) {
            unsigned long long a, b, c, d;
            asm volatile("ld.global.L2::evict_last.v4.b64 {%0,%1,%2,%3}, [%4];"
                         : "=l"(a), "=l"(b), "=l"(c), "=l"(d)
                         : "l"(obase + i * 32));
            s += a ^ b ^ c ^ d;
        }
        if (s == 0x123456789abcdefULL) g_dummy = 1.0f;   // defeats DCE
        return;
    }

    // ---- qkv GEMV block ----
    int qb  = bid - bid / 5;                     // dense remap 0..1279
    int rl  = tid >> 7;                          // row within block (0..1)
    int t   = tid & 127;
    int row = qb * 2 + rl;
    const float4* Wr = reinterpret_cast<const float4*>(W + (size_t)row * HIDDEN);
    const float4* x4 = reinterpret_cast<const float4*>(x);

    float4 w0 = __ldcs(&Wr[t]);
    float4 w1 = __ldcs(&Wr[t + 128]);
    float4 w2 = __ldcs(&Wr[t + 256]);
    float4 w3 = __ldcs(&Wr[t + 384]);
    float4 v0 = __ldg(&x4[t]);
    float4 v1 = __ldg(&x4[t + 128]);
    float4 v2 = __ldg(&x4[t + 256]);
    float4 v3 = __ldg(&x4[t + 384]);

    float acc = dot4(w0, v0) + dot4(w1, v1) + dot4(w2, v2) + dot4(w3, v3);

    acc = warp_sum(acc);
    __shared__ float swarp[8];
    int warp = tid >> 5, lane = tid & 31;
    if (lane == 0) swarp[warp] = acc;
    __syncthreads();
    if (tid < 2) {
        float r = swarp[4 * tid] + swarp[4 * tid + 1] +
                  swarp[4 * tid + 2] + swarp[4 * tid + 3];
        y[qb * 2 + tid] = r;
    }
}

// ---------------- phase D: output GEMV (o_w L2-hot) ------------------------
__global__ void gemv_o_kernel(const float* __restrict__ W,
                              const float* __restrict__ x,
                              float* __restrict__ y) {
    int tid = threadIdx.x;
    int rl  = tid >> 7;
    int t   = tid & 127;
    int row = blockIdx.x * 2 + rl;
    const float4* Wr = reinterpret_cast<const float4*>(W + (size_t)row * HIDDEN);
    const float4* x4 = reinterpret_cast<const float4*>(x);

    float4 w0 = Wr[t];            // L2 hits (prefetched evict_last)
    float4 w1 = Wr[t + 128];
    float4 w2 = Wr[t + 256];
    float4 w3 = Wr[t + 384];
    float4 v0 = __ldg(&x4[t]);
    float4 v1 = __ldg(&x4[t + 128]);
    float4 v2 = __ldg(&x4[t + 256]);
    float4 v3 = __ldg(&x4[t + 384]);

    float acc = dot4(w0, v0) + dot4(w1, v1) + dot4(w2, v2) + dot4(w3, v3);

    acc = warp_sum(acc);
    __shared__ float swarp[8];
    int warp = tid >> 5, lane = tid & 31;
    if (lane == 0) swarp[warp] = acc;
    __syncthreads();
    if (tid < 2) {
        float r = swarp[4 * tid] + swarp[4 * tid + 1] +
                  swarp[4 * tid + 2] + swarp[4 * tid + 3];
        y[blockIdx.x * 2 + tid] = r;
    }
}

// ---------------- fused attention: norm+rope + scores + exp + partial PV ---
__global__ void fused_attn_kernel(const float* __restrict__ kc,
                                  const float* __restrict__ vc,
                                  const float* __restrict__ mask,
                                  const float* __restrict__ cosv,
                                  const float* __restrict__ sinv,
                                  const float* __restrict__ qw,
                                  const float* __restrict__ kw,
                                  const int* __restrict__ kvidx) {
    __shared__ float sq[NQ * HD];
    __shared__ float sk[HD];
    __shared__ float sexp[CHUNK * NQ];
    __shared__ float smask[CHUNK];
    __shared__ int   sany;

    int c    = blockIdx.x;
    int tid  = threadIdx.x;
    int warp = tid >> 5, lane = tid & 31;
    int s0   = c * CHUNK;

    if (tid == 0) sany = 0;
    __syncthreads();
    if (tid < CHUNK) {
        float m = mask[s0 + tid];
        smask[tid] = m;
        if (m > -1e8f) atomicOr(&sany, 1);
    }
    __syncthreads();
    if (!sany) {
        if (tid < NQ) g_l[c * NQ + tid] = 0.0f;
        return;
    }

    // --- norm + rope (recomputed per block; L2-resident) -------------------
    for (int head = warp; head < 9; head += 8) {
        float x[8];
#pragma unroll
        for (int j = 0; j < 8; j++) x[j] = g_qkv[head * HD + lane + 32 * j];
        float mv = 0.f;
#pragma unroll
        for (int j = 0; j < 8; j++) mv = fmaxf(mv, fabsf(x[j]));
        mv = warp_max(mv);
        mv = fmaxf(mv, 5.9604644775390625e-8f);   // 2^-24
        float ss = 0.f, xs[8];
#pragma unroll
        for (int j = 0; j < 8; j++) { xs[j] = x[j] / mv; ss += xs[j] * xs[j]; }
        ss = warp_sum(ss);
        float rs = rsqrtf(ss);
        const float* wv = (head < NQ) ? qw : kw;
        float y[8];
#pragma unroll
        for (int j = 0; j < 8; j++) {
            int d = lane + 32 * j;
            y[j] = rs * 16.0f * xs[j] * (1.0f + wv[d]);
        }
#pragma unroll
        for (int j = 0; j < 8; j++) {
            int d = lane + 32 * j;
            float rot = (j < 4) ? -y[j ^ 4] : y[j ^ 4];
            float out = y[j] * cosv[d] + rot * sinv[d];
            if (head < NQ) sq[head * HD + d] = out * 0.0625f;  // * 256^-0.5
            else           sk[d] = out;
        }
    }
    __syncthreads();

    int pos = *kvidx;
    const float* kbase = kc + (size_t)LAYER * SEQ * HD;

    // --- scores -> softcap -> exp (warp per 4 positions, batched) ----------
    {
        float acc[4][NQ];
        const float4* k4p[4];
#pragma unroll
        for (int r = 0; r < 4; r++) {
            int sl = warp * 4 + r;
            int s = s0 + sl;
            const float* krow = (s == pos) ? sk : (kbase + (size_t)s * HD);
            k4p[r] = reinterpret_cast<const float4*>(krow);
#pragma unroll
            for (int h = 0; h < NQ; h++) acc[r][h] = 0.f;
        }
#pragma unroll
        for (int i = 0; i < 2; i++) {
            int idx = i * 32 + lane;
            float4 kv[4];
#pragma unroll
            for (int r = 0; r < 4; r++) kv[r] = k4p[r][idx];
#pragma unroll
            for (int h = 0; h < NQ; h++) {
                const float4* q4 = reinterpret_cast<const float4*>(&sq[h * HD]);
                float4 qv = q4[idx];
#pragma unroll
                for (int r = 0; r < 4; r++)
                    acc[r][h] += dot4(kv[r], qv);
            }
        }
#pragma unroll
        for (int r = 0; r < 4; r++) {
            int sl = warp * 4 + r;
            float m = smask[sl];
#pragma unroll
            for (int h = 0; h < NQ; h++) {
                float v = warp_sum(acc[r][h]);
                if (lane == h)
                    sexp[sl * NQ + h] = (m < -1e8f) ? 0.0f
                                      : expf(tanhf(v * 0.02f) * 50.0f + m);
            }
        }
    }
    __syncthreads();

    // --- per-head exp-sum ---------------------------------------------------
    if (warp < NQ) {
        float l = sexp[lane * NQ + warp];
        l = warp_sum(l);
        if (lane == 0) g_l[c * NQ + warp] = l;
    }

    // --- partial P.V (thread = dim d) ---------------------------------------
    const float* vbase = vc + (size_t)LAYER * SEQ * HD;
    const float* vnew  = g_qkv + 9 * HD;
    int d = tid;
    float acc[NQ] = {0, 0, 0, 0, 0, 0, 0, 0};
#pragma unroll 8
    for (int sl = 0; sl < CHUNK; sl++) {
        int s = s0 + sl;
        float v = (s == pos) ? vnew[d] : __ldcs(&vbase[(size_t)s * HD + d]);
#pragma unroll
        for (int h = 0; h < NQ; h++) acc[h] += sexp[sl * NQ + h] * v;
    }
#pragma unroll
    for (int h = 0; h < NQ; h++)
        g_part[(c * NQ + h) * HD + d] = acc[h];
}

// ---------------- combine partials across chunks ---------------------------
__global__ void combine_kernel() {
    int h  = blockIdx.x;
    int d0 = blockIdx.y * 32;
    int tid = threadIdx.x;
    int g  = tid >> 5;          // chunk group 0..7
    int dl = tid & 31;
    int d  = d0 + dl;

    __shared__ float sl[NCHUNK];
    sl[tid] = g_l[tid * NQ + h];
    __syncthreads();

    float acc = 0.f, L = 0.f;
#pragma unroll
    for (int k = 0; k < 32; k++) {
        int c = g * 32 + k;
        float l = sl[c];
        if (l > 0.f) {
            L += l;
            acc += g_part[(c * NQ + h) * HD + d];
        }
    }
    __shared__ float sacc[8][32];
    __shared__ float sLr[8][32];
    sacc[g][dl] = acc;
    sLr[g][dl]  = L;
    __syncthreads();
    if (g == 0) {
        float a = 0.f, Lt = 0.f;
#pragma unroll
        for (int k = 0; k < 8; k++) { a += sacc[k][dl]; Lt += sLr[k][dl]; }
        g_attn[h * HD + d] = a / Lt;
    }
}

// ---------------- launch ----------------------------------------------------
extern "C" void kernel_launch(void* const* d_in, const int* in_sizes, int n_in,
                              void* d_out, int out_size) {
    const float* hs   = (const float*)d_in[0];   // hidden_states (2048)
    const float* cosv = (const float*)d_in[1];   // cos (256)
    const float* sinv = (const float*)d_in[2];   // sin (256)
    const int*   kvix = (const int*)  d_in[3];   // kv_write_indices (1)
    const float* kc   = (const float*)d_in[4];   // k_cache
    const float* vc   = (const float*)d_in[5];   // v_cache
    const float* mask = (const float*)d_in[6];   // mask (8192)
    const float* qkvw = (const float*)d_in[7];   // qkv_w (2560x2048)
    const float* ow   = (const float*)d_in[8];   // o_w   (2048x2048)
    const float* qnw  = (const float*)d_in[9];   // q_norm_w (256)
    const float* knw  = (const float*)d_in[10];  // k_norm_w (256)
    float* out = (float*)d_out;

    void* p_qkv = nullptr;
    void* p_attn = nullptr;
    cudaGetSymbolAddress(&p_qkv, g_qkv);
    cudaGetSymbolAddress(&p_attn, g_attn);

    qkv_pref_kernel<<<PHASEA_GRID, 256>>>(qkvw, hs, (float*)p_qkv, ow);
    fused_attn_kernel<<<NCHUNK, 256>>>(kc, vc, mask, cosv, sinv, qnw, knw, kvix);
    combine_kernel<<<dim3(NQ, 8), 256>>>();
    gemv_o_kernel<<<HIDDEN / 2, 256>>>(ow, (const float*)p_attn, out);
}

// round 12
// speedup vs baseline: 1.2896x; 1.2896x over previous
#include <cuda_runtime.h>
#include <math.h>

#define HIDDEN   2048
#define NQ       8
#define HD       256
#define QKV_ROWS 2560   // (8 + 2) * 256
#define SEQ      8192
#define LAYER    5
#define CHUNK    32
#define NCHUNK   256    // SEQ / CHUNK

// ---------------- scratch (device globals; no allocation) ----------------
__device__ __align__(16) float g_qkv[QKV_ROWS];
__device__ __align__(16) float g_part[NCHUNK * NQ * HD];
__device__ __align__(16) float g_l[NCHUNK * NQ];
__device__ __align__(16) float g_attn[NQ * HD];

__device__ __forceinline__ float warp_sum(float v) {
#pragma unroll
    for (int o = 16; o; o >>= 1) v += __shfl_xor_sync(0xffffffffu, v, o);
    return v;
}
__device__ __forceinline__ float warp_max(float v) {
#pragma unroll
    for (int o = 16; o; o >>= 1) v = fmaxf(v, __shfl_xor_sync(0xffffffffu, v, o));
    return v;
}
__device__ __forceinline__ float dot4(float4 a, float4 b) {
    return a.x * b.x + a.y * b.y + a.z * b.z + a.w * b.w;
}

// ---------------- GEMV: 2 rows/block, 128 threads/row (R4/R7 best) ---------
__global__ void gemv_kernel(const float* __restrict__ W,
                            const float* __restrict__ x,
                            float* __restrict__ y) {
    int tid = threadIdx.x;
    int rl  = tid >> 7;            // row within block (0..1)
    int t   = tid & 127;           // thread within row
    int row = blockIdx.x * 2 + rl;
    const float4* Wr = reinterpret_cast<const float4*>(W + (size_t)row * HIDDEN);
    const float4* x4 = reinterpret_cast<const float4*>(x);

    float4 w0 = __ldcs(&Wr[t]);
    float4 w1 = __ldcs(&Wr[t + 128]);
    float4 w2 = __ldcs(&Wr[t + 256]);
    float4 w3 = __ldcs(&Wr[t + 384]);
    float4 v0 = __ldg(&x4[t]);
    float4 v1 = __ldg(&x4[t + 128]);
    float4 v2 = __ldg(&x4[t + 256]);
    float4 v3 = __ldg(&x4[t + 384]);

    float acc = dot4(w0, v0) + dot4(w1, v1) + dot4(w2, v2) + dot4(w3, v3);

    acc = warp_sum(acc);
    __shared__ float swarp[8];
    int warp = tid >> 5, lane = tid & 31;
    if (lane == 0) swarp[warp] = acc;
    __syncthreads();
    if (tid < 2) {
        float r = swarp[4 * tid] + swarp[4 * tid + 1] +
                  swarp[4 * tid + 2] + swarp[4 * tid + 3];
        y[blockIdx.x * 2 + tid] = r;
    }
}

// ---------------- fused attention (512 threads): halved latency chain ------
// Block c owns positions [c*32,(c+1)*32). 16 warps: scores = warp per
// 2 positions; P.V = two 256-thread groups each covering 16 positions,
// merged via smem. One-pass flash decode (softcap bounds scores).
__global__ void __launch_bounds__(512, 2)
fused_attn_kernel(const float* __restrict__ kc,
                  const float* __restrict__ vc,
                  const float* __restrict__ mask,
                  const float* __restrict__ cosv,
                  const float* __restrict__ sinv,
                  const float* __restrict__ qw,
                  const float* __restrict__ kw,
                  const int* __restrict__ kvidx) {
    __shared__ float sq[NQ * HD];          // 8 KB
    __shared__ float sk[HD];
    __shared__ float sexp[CHUNK * NQ];     // 1 KB
    __shared__ float smask[CHUNK];
    __shared__ float sup[NQ][HD];          // 8 KB (group-1 partials)
    __shared__ int   sany;

    int c    = blockIdx.x;
    int tid  = threadIdx.x;
    int warp = tid >> 5, lane = tid & 31;
    int s0   = c * CHUNK;

    // --- phase 0: fully-masked chunks exit immediately --------------------
    if (tid == 0) sany = 0;
    __syncthreads();
    if (tid < CHUNK) {
        float m = mask[s0 + tid];
        smask[tid] = m;
        if (m > -1e8f) atomicOr(&sany, 1);
    }
    __syncthreads();
    if (!sany) {
        if (tid < NQ) g_l[c * NQ + tid] = 0.0f;
        return;
    }

    // --- phase 1: norm + rope (warp per head; heads 0-7 = Q, 8 = K) -------
    if (warp < 9) {
        int head = warp;
        float x[8];
#pragma unroll
        for (int j = 0; j < 8; j++) x[j] = g_qkv[head * HD + lane + 32 * j];
        float mv = 0.f;
#pragma unroll
        for (int j = 0; j < 8; j++) mv = fmaxf(mv, fabsf(x[j]));
        mv = warp_max(mv);
        mv = fmaxf(mv, 5.9604644775390625e-8f);   // 2^-24
        float ss = 0.f, xs[8];
#pragma unroll
        for (int j = 0; j < 8; j++) { xs[j] = x[j] / mv; ss += xs[j] * xs[j]; }
        ss = warp_sum(ss);
        float rs = rsqrtf(ss);
        const float* wv = (head < NQ) ? qw : kw;
        float y[8];
#pragma unroll
        for (int j = 0; j < 8; j++) {
            int d = lane + 32 * j;
            y[j] = rs * 16.0f * xs[j] * (1.0f + wv[d]);
        }
#pragma unroll
        for (int j = 0; j < 8; j++) {
            int d = lane + 32 * j;
            float rot = (j < 4) ? -y[j ^ 4] : y[j ^ 4];
            float out = y[j] * cosv[d] + rot * sinv[d];
            if (head < NQ) sq[head * HD + d] = out * 0.0625f;  // * 256^-0.5
            else           sk[d] = out;
        }
    }
    __syncthreads();

    int pos = *kvidx;
    const float* kbase = kc + (size_t)LAYER * SEQ * HD;

    // --- phase 2: scores -> softcap -> exp (warp per 2 positions) ---------
    {
        float acc[2][NQ];
        const float4* k4p[2];
#pragma unroll
        for (int r = 0; r < 2; r++) {
            int sl = warp * 2 + r;
            int s = s0 + sl;
            const float* krow = (s == pos) ? sk : (kbase + (size_t)s * HD);
            k4p[r] = reinterpret_cast<const float4*>(krow);
#pragma unroll
            for (int h = 0; h < NQ; h++) acc[r][h] = 0.f;
        }
#pragma unroll
        for (int i = 0; i < 2; i++) {
            int idx = i * 32 + lane;
            float4 kv0 = k4p[0][idx];
            float4 kv1 = k4p[1][idx];
#pragma unroll
            for (int h = 0; h < NQ; h++) {
                const float4* q4 = reinterpret_cast<const float4*>(&sq[h * HD]);
                float4 qv = q4[idx];
                acc[0][h] += dot4(kv0, qv);
                acc[1][h] += dot4(kv1, qv);
            }
        }
#pragma unroll
        for (int r = 0; r < 2; r++) {
            int sl = warp * 2 + r;
            float m = smask[sl];
#pragma unroll
            for (int h = 0; h < NQ; h++) {
                float v = warp_sum(acc[r][h]);
                if (lane == h)
                    sexp[sl * NQ + h] = (m < -1e8f) ? 0.0f
                                      : expf(tanhf(v * 0.02f) * 50.0f + m);
            }
        }
    }
    __syncthreads();

    // --- phase 3: per-head exp-sum (warp h reduces column h over 32 sl) ---
    if (warp < NQ) {
        float l = sexp[lane * NQ + warp];
        l = warp_sum(l);
        if (lane == 0) g_l[c * NQ + warp] = l;
    }

    // --- phase 4: partial P.V, two 256-thread groups x 16 positions -------
    const float* vbase = vc + (size_t)LAYER * SEQ * HD;
    const float* vnew  = g_qkv + 9 * HD;
    int grp = tid >> 8;          // 0 or 1
    int d   = tid & 255;
    float acc[NQ] = {0, 0, 0, 0, 0, 0, 0, 0};
#pragma unroll 8
    for (int k = 0; k < CHUNK / 2; k++) {
        int sl = grp * (CHUNK / 2) + k;
        int s = s0 + sl;
        float v = (s == pos) ? vnew[d] : __ldcs(&vbase[(size_t)s * HD + d]);
#pragma unroll
        for (int h = 0; h < NQ; h++) acc[h] += sexp[sl * NQ + h] * v;
    }
    if (grp == 1) {
#pragma unroll
        for (int h = 0; h < NQ; h++) sup[h][d] = acc[h];
    }
    __syncthreads();
    if (grp == 0) {
#pragma unroll
        for (int h = 0; h < NQ; h++)
            g_part[(c * NQ + h) * HD + d] = acc[h] + sup[h][d];
    }
}

// ---------------- combine partials across chunks ---------------------------
__global__ void combine_kernel() {
    int h  = blockIdx.x;
    int d0 = blockIdx.y * 32;
    int tid = threadIdx.x;
    int g  = tid >> 5;          // chunk group 0..7
    int dl = tid & 31;
    int d  = d0 + dl;

    __shared__ float sl[NCHUNK];
    sl[tid] = g_l[tid * NQ + h];
    __syncthreads();

    float acc = 0.f, L = 0.f;
#pragma unroll
    for (int k = 0; k < 32; k++) {
        int c = g * 32 + k;
        float l = sl[c];
        if (l > 0.f) {
            L += l;
            acc += g_part[(c * NQ + h) * HD + d];
        }
    }
    __shared__ float sacc[8][32];
    __shared__ float sLr[8][32];
    sacc[g][dl] = acc;
    sLr[g][dl]  = L;
    __syncthreads();
    if (g == 0) {
        float a = 0.f, Lt = 0.f;
#pragma unroll
        for (int k = 0; k < 8; k++) { a += sacc[k][dl]; Lt += sLr[k][dl]; }
        g_attn[h * HD + d] = a / Lt;
    }
}

// ---------------- launch ----------------------------------------------------
extern "C" void kernel_launch(void* const* d_in, const int* in_sizes, int n_in,
                              void* d_out, int out_size) {
    const float* hs   = (const float*)d_in[0];   // hidden_states (2048)
    const float* cosv = (const float*)d_in[1];   // cos (256)
    const float* sinv = (const float*)d_in[2];   // sin (256)
    const int*   kvix = (const int*)  d_in[3];   // kv_write_indices (1)
    const float* kc   = (const float*)d_in[4];   // k_cache
    const float* vc   = (const float*)d_in[5];   // v_cache
    const float* mask = (const float*)d_in[6];   // mask (8192)
    const float* qkvw = (const float*)d_in[7];   // qkv_w (2560x2048)
    const float* ow   = (const float*)d_in[8];   // o_w   (2048x2048)
    const float* qnw  = (const float*)d_in[9];   // q_norm_w (256)
    const float* knw  = (const float*)d_in[10];  // k_norm_w (256)
    float* out = (float*)d_out;

    void* p_qkv = nullptr;
    void* p_attn = nullptr;
    cudaGetSymbolAddress(&p_qkv, g_qkv);
    cudaGetSymbolAddress(&p_attn, g_attn);

    gemv_kernel<<<QKV_ROWS / 2, 256>>>(qkvw, hs, (float*)p_qkv);
    fused_attn_kernel<<<NCHUNK, 512>>>(kc, vc, mask, cosv, sinv, qnw, knw, kvix);
    combine_kernel<<<dim3(NQ, 8), 256>>>();
    gemv_kernel<<<HIDDEN / 2, 256>>>(ow, (const float*)p_attn, out);
}